// round 4
// baseline (speedup 1.0000x reference)
#include <cuda_runtime.h>

// ProdAt: x [16384, 8192] fp32 -> out [16384, 128] fp32
// out[seg] = prod of 64 contiguous floats.
//
// Persistent grid-stride kernel: one wave of 1184 CTAs stays resident.
// Geometry per iteration (= R2 config, best measured):
//   8 lanes per segment; each lane loads f4[sub] and f4[sub+8] (each LDG.128
//   by an 8-lane group covers one full 128B line -> perfect coalescing).
//   Each thread handles 2 segments -> 4 independent LDG.128 in flight.
//   Reduction: two pipelined 3-step shfl_xor chains over the 8-lane group.

static constexpr long long N_SEGMENTS_TOTAL = 16384LL * 128LL;    // 2,097,152
static constexpr long long N_SEG8 = N_SEGMENTS_TOTAL / 8;         // 262,144 warp-chunks

__device__ __forceinline__ float prod4(float4 v) {
    return (v.x * v.y) * (v.z * v.w);
}

__global__ void __launch_bounds__(256) prodat_kernel(
    const float* __restrict__ x, float* __restrict__ out)
{
    const int warps_per_block = blockDim.x >> 5;
    const long long warp_id =
        (long long)blockIdx.x * warps_per_block + (threadIdx.x >> 5);
    const long long warp_stride = (long long)gridDim.x * warps_per_block;

    const int lane = threadIdx.x & 31;
    const int g    = lane >> 3;   // 0..3 : segment group within warp
    const int sub  = lane & 7;    // 0..7 : float4 slot within segment half

    const float4* x4 = reinterpret_cast<const float4*>(x);

    for (long long c = warp_id; c < N_SEG8; c += warp_stride) {
        // warp covers 8 consecutive segments [c*8, c*8+8)
        const long long seg0 = c * 8 + g;   // this thread: seg0 and seg0+4
        const long long seg1 = seg0 + 4;

        // front-batch 4 independent loads (MLP = 4)
        const float4 a0 = __ldcs(x4 + seg0 * 16 + sub);
        const float4 b0 = __ldcs(x4 + seg0 * 16 + 8 + sub);
        const float4 a1 = __ldcs(x4 + seg1 * 16 + sub);
        const float4 b1 = __ldcs(x4 + seg1 * 16 + 8 + sub);

        float p0 = prod4(a0) * prod4(b0);
        float p1 = prod4(a1) * prod4(b1);

        #pragma unroll
        for (int off = 4; off > 0; off >>= 1) {
            p0 *= __shfl_xor_sync(0xffffffffu, p0, off);
            p1 *= __shfl_xor_sync(0xffffffffu, p1, off);
        }

        if (sub == 0) {
            out[seg0] = p0;
            out[seg1] = p1;
        }
    }
}

extern "C" void kernel_launch(void* const* d_in, const int* in_sizes, int n_in,
                              void* d_out, int out_size)
{
    const float* x = (const float*)d_in[0];
    float* out = (float*)d_out;

    // Persistent single-wave grid: 148 SMs x 8 CTAs (256 thr, 32 regs -> fits)
    const int threads = 256;
    const int blocks = 148 * 8;  // 1184

    prodat_kernel<<<blocks, threads>>>(x, out);
}

// round 5
// speedup vs baseline: 1.0508x; 1.0508x over previous
#include <cuda_runtime.h>

// ProdAt: x [16384, 8192] fp32 -> out [16384, 128] fp32
// out[seg] = prod of 64 contiguous floats.
//
// Best-known geometry (R2) + micro-tweaks:
//   8 lanes per segment; each lane loads f4[sub] and f4[sub+8] (each LDG.128
//   by an 8-lane group covers one full 128B line -> perfect coalescing).
//   Each thread handles 2 ADJACENT segments (2g, 2g+1) -> 4 independent
//   LDG.128 in flight (MLP=4), and sub==0 lanes store a packed float2
//   (STG.64; warp writes 32B fully-covered sectors).
//   512-thread blocks to halve CTA count.

static constexpr long long N_SEGMENTS_TOTAL = 16384LL * 128LL;  // 2,097,152

__device__ __forceinline__ float prod4(float4 v) {
    return (v.x * v.y) * (v.z * v.w);
}

__global__ void __launch_bounds__(512) prodat_kernel(
    const float* __restrict__ x, float* __restrict__ out)
{
    const long long warp_id =
        (long long)blockIdx.x * (blockDim.x >> 5) + (threadIdx.x >> 5);
    const int lane = threadIdx.x & 31;

    const int g   = lane >> 3;   // 0..3 : segment-pair group within warp
    const int sub = lane & 7;    // 0..7 : float4 slot within segment half

    // warp covers 8 consecutive segments [warp_id*8, warp_id*8+8)
    // this thread: adjacent segments 2g and 2g+1
    const long long seg0 = warp_id * 8 + 2 * g;
    const long long seg1 = seg0 + 1;

    const float4* x4 = reinterpret_cast<const float4*>(x);

    // front-batch 4 independent loads (MLP = 4)
    const float4 a0 = __ldcs(x4 + seg0 * 16 + sub);
    const float4 b0 = __ldcs(x4 + seg0 * 16 + 8 + sub);
    const float4 a1 = __ldcs(x4 + seg1 * 16 + sub);
    const float4 b1 = __ldcs(x4 + seg1 * 16 + 8 + sub);

    float p0 = prod4(a0) * prod4(b0);
    float p1 = prod4(a1) * prod4(b1);

    // two independent 3-step reductions over the 8-lane group (pipelined)
    #pragma unroll
    for (int off = 4; off > 0; off >>= 1) {
        p0 *= __shfl_xor_sync(0xffffffffu, p0, off);
        p1 *= __shfl_xor_sync(0xffffffffu, p1, off);
    }

    if (sub == 0) {
        // packed 8B store of two adjacent segment results
        reinterpret_cast<float2*>(out)[seg0 >> 1] = make_float2(p0, p1);
    }
}

extern "C" void kernel_launch(void* const* d_in, const int* in_sizes, int n_in,
                              void* d_out, int out_size)
{
    const float* x = (const float*)d_in[0];
    float* out = (float*)d_out;

    // 512 threads = 16 warps = 128 segments per block
    const int threads = 512;
    const long long blocks = N_SEGMENTS_TOTAL / 128;  // 16384, exact

    prodat_kernel<<<(unsigned)blocks, threads>>>(x, out);
}